// round 15
// baseline (speedup 1.0000x reference)
#include <cuda_runtime.h>
#include <cuda_bf16.h>
#include <math.h>

#define B_  4
#define N_  2048
#define D_  512
#define H_  8
#define DH_ 64
#define M_  (B_*N_)      /* 8192 rows */

// packed bf16-pair (uint) row strides
#define HP   256          // g_h:   512 bf16 = 256 uints
#define QKVP 768          // g_qkv: 1536 bf16 = 768 uints (q|k|v)
#define AOP  256          // g_ao

// ---------------- scratch (no cudaMalloc allowed) ----------------
__device__ __align__(16) unsigned g_h  [(size_t)M_ * HP];    // 8 MB
__device__ __align__(16) unsigned g_qkv[(size_t)M_ * QKVP];  // 24 MB
__device__ __align__(16) unsigned g_ao [(size_t)M_ * AOP];   // 8 MB
__device__ __align__(16) unsigned g_wpk[4 * 512 * 256];      // 2 MB bf16 weights

// ---------------- helpers ----------------
__device__ __forceinline__ unsigned pkbf(float lo, float hi) {
    unsigned d;
    asm("cvt.rn.bf16x2.f32 %0, %1, %2;" : "=r"(d) : "f"(hi), "f"(lo));
    return d;
}
__device__ __forceinline__ void mma_bf16(float c[4],
    unsigned a0, unsigned a1, unsigned a2, unsigned a3,
    unsigned b0, unsigned b1)
{
    asm volatile(
        "mma.sync.aligned.m16n8k16.row.col.f32.bf16.bf16.f32 "
        "{%0,%1,%2,%3}, {%4,%5,%6,%7}, {%8,%9}, {%0,%1,%2,%3};"
        : "+f"(c[0]), "+f"(c[1]), "+f"(c[2]), "+f"(c[3])
        : "r"(a0), "r"(a1), "r"(a2), "r"(a3), "r"(b0), "r"(b1));
}
__device__ __forceinline__ void ldsm4(unsigned d[4], unsigned addr) {
    asm volatile("ldmatrix.sync.aligned.m8n8.x4.shared.b16 {%0,%1,%2,%3}, [%4];"
        : "=r"(d[0]), "=r"(d[1]), "=r"(d[2]), "=r"(d[3]) : "r"(addr));
}
__device__ __forceinline__ void ldsm4t(unsigned d[4], unsigned addr) {
    asm volatile("ldmatrix.sync.aligned.m8n8.x4.trans.shared.b16 {%0,%1,%2,%3}, [%4];"
        : "=r"(d[0]), "=r"(d[1]), "=r"(d[2]), "=r"(d[3]) : "r"(addr));
}
__device__ __forceinline__ void cp16(unsigned dst, const void* src) {
    asm volatile("cp.async.cg.shared.global [%0], [%1], 16;"
                 :: "r"(dst), "l"(src));
}
#define CPCOMMIT() asm volatile("cp.async.commit_group;")
#define CPWAIT(n)  asm volatile("cp.async.wait_group %0;" :: "n"(n))

// softmax scale folded into Q, times 2^7 so MMA emits s = 128*log2-score.
#define SCQ7   23.083120654223414f   /* (1/8)*log2(e)*128 */
// Schraudolph bf16 exp2: bf16_bits(2^(s/128)) ~= rni(s + 127*128 - sigma*128)
#define MAGICF 16251.5f              /* 16256 - 0.0351*128 */

// ====== fused: LayerNorm+pe (blocks 0..8191) | weight prepack (8192..12287)
__global__ __launch_bounds__(128) void ln_prepack_kernel(
    const float* __restrict__ x, const float* __restrict__ w,
    const float* __restrict__ bias, const float* __restrict__ pe,
    unsigned* __restrict__ h,
    const float* __restrict__ wq, const float* __restrict__ wk,
    const float* __restrict__ wv, const float* __restrict__ wo,
    unsigned* __restrict__ wpk)
{
    int t = threadIdx.x;
    if (blockIdx.x >= M_) {          // ---- prepack branch ----
        int idx = (blockIdx.x - M_) * 128 + t;
        int m = idx >> 17, rem = idx & 0x1FFFF;
        int k = rem >> 8, nu = rem & 255;
        const float* ww = (m == 0) ? wq : (m == 1) ? wk : (m == 2) ? wv : wo;
        wpk[idx] = pkbf(ww[k * 512 + 2 * nu], ww[k * 512 + 2 * nu + 1]);
        return;
    }
    int row = blockIdx.x;
    float4 v = ((const float4*)(x + (size_t)row * D_))[t];
    float s  = v.x + v.y + v.z + v.w;
    float sq = v.x*v.x + v.y*v.y + v.z*v.z + v.w*v.w;
    #pragma unroll
    for (int off = 16; off; off >>= 1) {
        s  += __shfl_xor_sync(0xffffffffu, s,  off);
        sq += __shfl_xor_sync(0xffffffffu, sq, off);
    }
    __shared__ float ss[4], sq4[4];
    int wid = t >> 5, ln = t & 31;
    if (ln == 0) { ss[wid] = s; sq4[wid] = sq; }
    __syncthreads();
    s  = ss[0]  + ss[1]  + ss[2]  + ss[3];
    sq = sq4[0] + sq4[1] + sq4[2] + sq4[3];
    float mean = s * (1.0f / D_);
    float var  = sq * (1.0f / D_) - mean * mean;
    float rstd = rsqrtf(var + 1e-5f);
    int n = row & (N_ - 1);
    float4 pv = ((const float4*)(pe + (size_t)n * D_))[t];
    float4 wv4 = ((const float4*)w)[t];
    float4 bv4 = ((const float4*)bias)[t];
    float ox = (v.x - mean) * rstd * wv4.x + bv4.x + pv.x;
    float oy = (v.y - mean) * rstd * wv4.y + bv4.y + pv.y;
    float oz = (v.z - mean) * rstd * wv4.z + bv4.z + pv.z;
    float ow = (v.w - mean) * rstd * wv4.w + bv4.w + pv.w;
    ((uint2*)(h + (size_t)row * HP))[t] = make_uint2(pkbf(ox, oy), pkbf(oz, ow));
}

// ================= bf16 tensor-core GEMM, static 3-stage pipeline ==========
// MODE 0: fused QKV  — A=g_h, weight by blockIdx.x>>2; Q pre-scaled by SCQ7;
//                      bias=bv for wsel==2; out bf16 -> g_qkv
// MODE 1: out proj   — A=g_ao, weight wo, +bo +residual x, out fp32
template<int MODE>
__global__ __launch_bounds__(256, 2) void gemm_bf16(
    const unsigned* __restrict__ Apk, const unsigned* __restrict__ wpk,
    const float* __restrict__ bias, const float* __restrict__ res,
    float* __restrict__ Cf, unsigned* __restrict__ Cu)
{
    extern __shared__ unsigned dsm[];
    unsigned* As = dsm;           // 3 bufs x 128 x 36
    unsigned* Bs = dsm + 13824;   // 3 bufs x 64 x 68

    int tid  = threadIdx.x, lane = tid & 31, warp = tid >> 5;
    int li = lane >> 3, lr = lane & 7;
    int g = lane >> 2, t = lane & 3;
    int wm = (warp >> 2) * 64, wn = (warp & 3) * 32;
    int wn2 = (warp & 3) * 16;

    int cb    = blockIdx.x;
    int wsel  = (MODE == 0) ? (cb >> 2) : 3;
    int ncol0 = (MODE == 0) ? (cb & 3) * 128 : cb * 128;
    const unsigned* Bb = wpk + wsel * (512 * 256) + ncol0 / 2;
    const unsigned* Ab = Apk + (size_t)blockIdx.y * 128 * HP;

    int ar = tid >> 1, apc = (tid & 1) * 16;
    int br = tid >> 2, bcc = (tid & 3) * 16;
    unsigned sA = (unsigned)__cvta_generic_to_shared(As);
    unsigned sB = (unsigned)__cvta_generic_to_shared(Bs);

    int arow = 8 * (li & 1) + lr;
    int acol = (li >> 1) * 4;
    int bcol = (li >> 1) * 4;

    float acc[4][4][4];
    #pragma unroll
    for (int mi = 0; mi < 4; mi++)
        #pragma unroll
        for (int ni = 0; ni < 4; ni++)
            #pragma unroll
            for (int r = 0; r < 4; r++) acc[mi][ni][r] = 0.0f;

    auto stage = [&](int s, int buf) {
        unsigned da = sA + (buf * 4608 + ar * 36 + apc) * 4;
        const unsigned* ga = Ab + (size_t)ar * HP + s * 32 + apc;
        #pragma unroll
        for (int i = 0; i < 4; i++) cp16(da + i * 16, ga + i * 4);
        unsigned db = sB + (buf * 4352 + br * 68 + bcc) * 4;
        const unsigned* gb = Bb + (size_t)(s * 64 + br) * 256 + bcc;
        #pragma unroll
        for (int i = 0; i < 4; i++) cp16(db + i * 16, gb + i * 4);
        CPCOMMIT();
    };

    stage(0, 0);
    stage(1, 1);
    CPWAIT(1);
    __syncthreads();

#define GBODY(s, BUF, PBUF)                                                  \
    do {                                                                     \
        if ((s) + 2 < 8) stage((s) + 2, (PBUF));                             \
        unsigned baseA = sA + (BUF) * 18432;                                 \
        unsigned baseB = sB + (BUF) * 17408;                                 \
        _Pragma("unroll")                                                    \
        for (int kk = 0; kk < 4; kk++) {                                     \
            unsigned af[4][4];                                               \
            _Pragma("unroll")                                                \
            for (int mi = 0; mi < 4; mi++)                                   \
                ldsm4(af[mi], baseA +                                        \
                      ((wm + mi * 16 + arow) * 36 + kk * 8 + acol) * 4);     \
            unsigned bb[8];                                                  \
            _Pragma("unroll")                                                \
            for (int j = 0; j < 2; j++)                                      \
                ldsm4t(bb + 4 * j, baseB +                                   \
                       ((kk * 16 + arow) * 68 + wn2 + j * 8 + bcol) * 4);    \
            _Pragma("unroll")                                                \
            for (int mi = 0; mi < 4; mi++)                                   \
                _Pragma("unroll")                                            \
                for (int ni = 0; ni < 4; ni++)                               \
                    mma_bf16(acc[mi][ni], af[mi][0], af[mi][1], af[mi][2],   \
                             af[mi][3],                                      \
                             bb[4 * (ni >> 1) + 2 * (ni & 1)],               \
                             bb[4 * (ni >> 1) + 2 * (ni & 1) + 1]);          \
        }                                                                    \
        if ((s) < 6) { CPWAIT(1); __syncthreads(); }                         \
        else if ((s) == 6) { CPWAIT(0); __syncthreads(); }                   \
    } while (0)

    GBODY(0, 0, 2); GBODY(1, 1, 0); GBODY(2, 2, 1); GBODY(3, 0, 2);
    GBODY(4, 1, 0); GBODY(5, 2, 1); GBODY(6, 0, 2); GBODY(7, 1, 0);
#undef GBODY

    #pragma unroll
    for (int mi = 0; mi < 4; mi++) {
        int r0 = blockIdx.y * 128 + wm + mi * 16 + g;
        #pragma unroll
        for (int ni = 0; ni < 4; ni++) {
            int ec = ncol0 + wn + ni * 8 + 2 * t;
            float v0 = acc[mi][ni][0], v1 = acc[mi][ni][1];
            float v2 = acc[mi][ni][2], v3 = acc[mi][ni][3];
            if (MODE == 0) {
                if (wsel == 0) {
                    v0 *= SCQ7; v1 *= SCQ7; v2 *= SCQ7; v3 *= SCQ7;
                }
                if (wsel == 2) {
                    float2 bb2 = *(const float2*)(bias + ec);
                    v0 += bb2.x; v1 += bb2.y; v2 += bb2.x; v3 += bb2.y;
                }
                unsigned ucol = wsel * 256 + (ec >> 1);
                Cu[(size_t)r0 * QKVP + ucol]       = pkbf(v0, v1);
                Cu[(size_t)(r0 + 8) * QKVP + ucol] = pkbf(v2, v3);
            } else {
                float2 bb2 = *(const float2*)(bias + ec);
                size_t o0 = (size_t)r0 * 512 + ec;
                size_t o1 = (size_t)(r0 + 8) * 512 + ec;
                float2 ra = *(const float2*)(res + o0);
                float2 rb = *(const float2*)(res + o1);
                *(float2*)(Cf + o0) = make_float2(v0 + bb2.x + ra.x, v1 + bb2.y + ra.y);
                *(float2*)(Cf + o1) = make_float2(v2 + bb2.x + rb.x, v3 + bb2.y + rb.y);
            }
        }
    }
}

// ================= flash attention: pingpong + ALU row-sum =================
// 256 thr / 8 warps, q-tile 128, key chunk 64, 2 CTAs/SM, 4 static buffers,
// prefetch distance 3. Body(c): softmax(c) (Schraudolph; row-sum l
// accumulated on ALU from exact bf16 bit values) -> S(c+1) MMAs -> PV(c).
// No L-MMA: tensor pipe only does S and PV.
__global__ __launch_bounds__(256, 2) void attn_kernel(
    const unsigned* __restrict__ qkv, unsigned* __restrict__ ao)
{
    extern __shared__ unsigned asm_[];
    unsigned* Ks = asm_;              // 4 bufs x 64 x 36
    unsigned* Vs = asm_ + 4 * 2304;   // 4 bufs x 64 x 36

    int tid = threadIdx.x, lane = tid & 31, warp = tid >> 5;
    int g = lane >> 2, t = lane & 3;
    int li = lane >> 3, lr = lane & 7;
    int bh = blockIdx.y, bb = bh >> 3, hh = bh & 7;
    int q0 = blockIdx.x * 128;
    const unsigned* base = qkv + (size_t)bb * N_ * QKVP + hh * 32;

    int kcr = tid >> 2, kcp = (tid & 3) * 8;   // copy: row, uint col
    unsigned sK = (unsigned)__cvta_generic_to_shared(Ks);
    unsigned sV = (unsigned)__cvta_generic_to_shared(Vs);

    // ldmatrix lane constants
    int krow = (li >> 1) * 8 + lr;
    int kcol = (li & 1) * 4;
    int vrow = (li & 1) * 8 + lr;
    int vcol = (li >> 1) * 4;

    auto cpKV = [&](int c0, int buf) {
        const unsigned* src = base + (size_t)(c0 + kcr) * QKVP + 256 + kcp;
        unsigned dK = sK + (buf * 2304 + kcr * 36 + kcp) * 4;
        cp16(dK, src); cp16(dK + 16, src + 4);
        unsigned dV = sV + (buf * 2304 + kcr * 36 + kcp) * 4;
        cp16(dV, src + 256); cp16(dV + 16, src + 260);
        CPCOMMIT();
    };

    // prologue: chunks 0,1,2 in flight + Q fragments
    cpKV(0, 0);
    cpKV(64, 1);
    cpKV(128, 2);
    unsigned qf[4][4];
    {
        const unsigned* q0p = base + (size_t)(q0 + warp * 16 + g) * QKVP;
        const unsigned* q1p = q0p + 8 * QKVP;
        #pragma unroll
        for (int kk = 0; kk < 4; kk++) {
            qf[kk][0] = q0p[kk * 8 + t];
            qf[kk][1] = q1p[kk * 8 + t];
            qf[kk][2] = q0p[kk * 8 + t + 4];
            qf[kk][3] = q1p[kk * 8 + t + 4];
        }
    }
    CPWAIT(1);          // chunks 0,1 resident (chunk 2 may still fly)
    __syncthreads();

    float o[8][4], s[8][4];
    #pragma unroll
    for (int ni = 0; ni < 8; ni++)
        #pragma unroll
        for (int r = 0; r < 4; r++) { o[ni][r] = 0.0f; s[ni][r] = 0.0f; }
    float lsum0 = 0.0f, lsum1 = 0.0f;   // row sums (rows g, g+8)

// S += Q @ K(buffer NB)^T
#define SMMA(NB)                                                             \
    do {                                                                     \
        unsigned baseK = sK + (NB) * 9216;                                   \
        _Pragma("unroll")                                                    \
        for (int kk = 0; kk < 4; kk++) {                                     \
            unsigned kb[16];                                                 \
            _Pragma("unroll")                                                \
            for (int j = 0; j < 4; j++)                                      \
                ldsm4(kb + 4 * j, baseK +                                    \
                      ((j * 16 + krow) * 36 + kk * 8 + kcol) * 4);           \
            _Pragma("unroll")                                                \
            for (int ni = 0; ni < 8; ni++)                                   \
                mma_bf16(s[ni], qf[kk][0], qf[kk][1], qf[kk][2], qf[kk][3],  \
                         kb[4 * (ni >> 1) + 2 * (ni & 1)],                   \
                         kb[4 * (ni >> 1) + 2 * (ni & 1) + 1]);              \
        }                                                                    \
    } while (0)

    SMMA(0);

// Body(c). BUF=c&3 (V read), NBUF=(c+1)&3 (K read), CPBUF=(c+3)&3 (cp tgt).
#define CHUNK(c, BUF, NBUF, CPBUF, WMODE, LAST)                              \
    do {                                                                     \
        if ((c) + 3 < 32) cpKV(((c) + 3) * 64, (CPBUF));                     \
        unsigned pa[4][4];                                                   \
        _Pragma("unroll")                                                    \
        for (int ni = 0; ni < 8; ni++) {                                     \
            int v0 = __float2int_rn(s[ni][0] + MAGICF);                      \
            int v1 = __float2int_rn(s[ni][1] + MAGICF);                      \
            int v2 = __float2int_rn(s[ni][2] + MAGICF);                      \
            int v3 = __float2int_rn(s[ni][3] + MAGICF);                      \
            /* exact P values for row sums (bf16 bits << 16) */              \
            lsum0 += __uint_as_float((unsigned)v0 << 16)                     \
                   + __uint_as_float((unsigned)v1 << 16);                    \
            lsum1 += __uint_as_float((unsigned)v2 << 16)                     \
                   + __uint_as_float((unsigned)v3 << 16);                    \
            int kk = ni >> 1, hf = ni & 1;                                   \
            pa[kk][2 * hf]     = __byte_perm(v0, v1, 0x5410);                \
            pa[kk][2 * hf + 1] = __byte_perm(v2, v3, 0x5410);                \
        }                                                                    \
        if (!(LAST)) {                                                       \
            _Pragma("unroll")                                                \
            for (int ni = 0; ni < 8; ni++) {                                 \
                s[ni][0] = 0.0f; s[ni][1] = 0.0f;                            \
                s[ni][2] = 0.0f; s[ni][3] = 0.0f;                            \
            }                                                                \
            SMMA(NBUF);                                                      \
        }                                                                    \
        unsigned baseV = sV + (BUF) * 9216;                                  \
        _Pragma("unroll")                                                    \
        for (int kk = 0; kk < 4; kk++) {                                     \
            unsigned vb[16];                                                 \
            _Pragma("unroll")                                                \
            for (int j = 0; j < 4; j++)                                      \
                ldsm4t(vb + 4 * j, baseV +                                   \
                       ((kk * 16 + vrow) * 36 + j * 8 + vcol) * 4);          \
            _Pragma("unroll")                                                \
            for (int ni = 0; ni < 8; ni++)                                   \
                mma_bf16(o[ni], pa[kk][0], pa[kk][1], pa[kk][2], pa[kk][3],  \
                         vb[4 * (ni >> 1) + 2 * (ni & 1)],                   \
                         vb[4 * (ni >> 1) + 2 * (ni & 1) + 1]);              \
        }                                                                    \
        if ((WMODE) == 0) { CPWAIT(1); __syncthreads(); }                    \
        else if ((WMODE) == 1) { CPWAIT(0); __syncthreads(); }               \
    } while (0)

    for (int c0 = 0; c0 < 28; c0 += 4) {
        CHUNK(c0,     0, 1, 3, 0, 0);
        CHUNK(c0 + 1, 1, 2, 0, 0, 0);
        CHUNK(c0 + 2, 2, 3, 1, 0, 0);
        CHUNK(c0 + 3, 3, 0, 2, 0, 0);
    }
    CHUNK(28, 0, 1, 3, 0, 0);
    CHUNK(29, 1, 2, 0, 1, 0);
    CHUNK(30, 2, 3, 1, 2, 0);
    CHUNK(31, 3, 0, 2, 2, 1);
#undef CHUNK
#undef SMMA

    // final row-sum across the 4-lane quad (t dimension), once
    lsum0 += __shfl_xor_sync(0xffffffffu, lsum0, 1);
    lsum0 += __shfl_xor_sync(0xffffffffu, lsum0, 2);
    lsum1 += __shfl_xor_sync(0xffffffffu, lsum1, 1);
    lsum1 += __shfl_xor_sync(0xffffffffu, lsum1, 2);

    // epilogue -> g_ao (bf16 packed)
    float i0 = 1.0f / lsum0, i1 = 1.0f / lsum1;
    int r0 = bb * N_ + q0 + warp * 16 + g;
    unsigned* a0p = ao + (size_t)r0 * AOP + hh * 32;
    unsigned* a1p = a0p + 8 * AOP;
    #pragma unroll
    for (int ni = 0; ni < 8; ni++) {
        a0p[ni * 4 + t] = pkbf(o[ni][0] * i0, o[ni][1] * i0);
        a1p[ni * 4 + t] = pkbf(o[ni][2] * i1, o[ni][3] * i1);
    }
}

// ================= launch ==========================
extern "C" void kernel_launch(void* const* d_in, const int* in_sizes, int n_in,
                              void* d_out, int out_size)
{
    const float* x    = (const float*)d_in[0];
    const float* ln_w = (const float*)d_in[1];
    const float* ln_b = (const float*)d_in[2];
    const float* wq   = (const float*)d_in[3];
    const float* wk   = (const float*)d_in[4];
    const float* wv   = (const float*)d_in[5];
    const float* bv   = (const float*)d_in[6];
    const float* wo   = (const float*)d_in[7];
    const float* bo   = (const float*)d_in[8];
    const float* pe   = (const float*)d_in[9];
    float* out = (float*)d_out;

    unsigned *hp, *qkvp, *aop, *wpk;
    cudaGetSymbolAddress((void**)&hp,   g_h);
    cudaGetSymbolAddress((void**)&qkvp, g_qkv);
    cudaGetSymbolAddress((void**)&aop,  g_ao);
    cudaGetSymbolAddress((void**)&wpk,  g_wpk);

    const int GSM  = 3 * (4608 + 4352) * 4;   // 107520 B
    const int ASMB = 4 * 2304 * 2 * 4;        // 73728 B
    cudaFuncSetAttribute(gemm_bf16<0>,
                         cudaFuncAttributeMaxDynamicSharedMemorySize, GSM);
    cudaFuncSetAttribute(gemm_bf16<1>,
                         cudaFuncAttributeMaxDynamicSharedMemorySize, GSM);
    cudaFuncSetAttribute(attn_kernel,
                         cudaFuncAttributeMaxDynamicSharedMemorySize, ASMB);

    // 1) LayerNorm + pe + weight prepack (one fused launch)
    ln_prepack_kernel<<<M_ + 4096, 128>>>(x, ln_w, ln_b, pe, hp,
                                          wq, wk, wv, wo, wpk);

    // 2) fused QKV projection (Q pre-scaled by SCQ7)
    gemm_bf16<0><<<dim3(12, M_ / 128), 256, GSM>>>(hp, wpk, bv, nullptr,
                                                   nullptr, qkvp);

    // 3) flash attention: pingpong S/PV, ALU row-sums
    attn_kernel<<<dim3(N_ / 128, B_ * H_), 256, ASMB>>>(qkvp, aop);

    // 4) output projection + bias + residual
    gemm_bf16<1><<<dim3(4, M_ / 128), 256, GSM>>>(aop, wpk, bo, x, out, nullptr);
}

// round 16
// speedup vs baseline: 1.0310x; 1.0310x over previous
#include <cuda_runtime.h>
#include <cuda_bf16.h>
#include <math.h>

#define B_  4
#define N_  2048
#define D_  512
#define H_  8
#define DH_ 64
#define M_  (B_*N_)      /* 8192 rows */

// packed bf16-pair (uint) row strides
#define HP   256          // g_h:   512 bf16 = 256 uints
#define QKVP 768          // g_qkv: 1536 bf16 = 768 uints (q|k|v)
#define AOP  256          // g_ao

// ---------------- scratch (no cudaMalloc allowed) ----------------
__device__ __align__(16) unsigned g_h  [(size_t)M_ * HP];    // 8 MB
__device__ __align__(16) unsigned g_qkv[(size_t)M_ * QKVP];  // 24 MB
__device__ __align__(16) unsigned g_ao [(size_t)M_ * AOP];   // 8 MB
__device__ __align__(16) unsigned g_wpk[4 * 512 * 256];      // 2 MB bf16 weights

// ---------------- helpers ----------------
__device__ __forceinline__ unsigned pkbf(float lo, float hi) {
    unsigned d;
    asm("cvt.rn.bf16x2.f32 %0, %1, %2;" : "=r"(d) : "f"(hi), "f"(lo));
    return d;
}
__device__ __forceinline__ void mma_bf16(float c[4],
    unsigned a0, unsigned a1, unsigned a2, unsigned a3,
    unsigned b0, unsigned b1)
{
    asm volatile(
        "mma.sync.aligned.m16n8k16.row.col.f32.bf16.bf16.f32 "
        "{%0,%1,%2,%3}, {%4,%5,%6,%7}, {%8,%9}, {%0,%1,%2,%3};"
        : "+f"(c[0]), "+f"(c[1]), "+f"(c[2]), "+f"(c[3])
        : "r"(a0), "r"(a1), "r"(a2), "r"(a3), "r"(b0), "r"(b1));
}
__device__ __forceinline__ void ldsm4(unsigned d[4], unsigned addr) {
    asm volatile("ldmatrix.sync.aligned.m8n8.x4.shared.b16 {%0,%1,%2,%3}, [%4];"
        : "=r"(d[0]), "=r"(d[1]), "=r"(d[2]), "=r"(d[3]) : "r"(addr));
}
__device__ __forceinline__ void ldsm4t(unsigned d[4], unsigned addr) {
    asm volatile("ldmatrix.sync.aligned.m8n8.x4.trans.shared.b16 {%0,%1,%2,%3}, [%4];"
        : "=r"(d[0]), "=r"(d[1]), "=r"(d[2]), "=r"(d[3]) : "r"(addr));
}
__device__ __forceinline__ void cp16(unsigned dst, const void* src) {
    asm volatile("cp.async.cg.shared.global [%0], [%1], 16;"
                 :: "r"(dst), "l"(src));
}
#define CPCOMMIT() asm volatile("cp.async.commit_group;")
#define CPWAIT(n)  asm volatile("cp.async.wait_group %0;" :: "n"(n))

// softmax scale folded into Q, times 2^7 so MMA emits s = 128*log2-score.
#define SCQ7   23.083120654223414f   /* (1/8)*log2(e)*128 */
// Schraudolph bf16 exp2: bf16_bits(2^(s/128)) ~= rni(s + 127*128 - sigma*128)
#define MAGICF 16251.5f              /* 16256 - 0.0351*128 */
#define ONESBF 0x3F803F80u           /* bf16x2 {1.0, 1.0} */

// ====== fused: LayerNorm+pe (blocks 0..8191) | weight prepack (8192..12287)
__global__ __launch_bounds__(128) void ln_prepack_kernel(
    const float* __restrict__ x, const float* __restrict__ w,
    const float* __restrict__ bias, const float* __restrict__ pe,
    unsigned* __restrict__ h,
    const float* __restrict__ wq, const float* __restrict__ wk,
    const float* __restrict__ wv, const float* __restrict__ wo,
    unsigned* __restrict__ wpk)
{
    int t = threadIdx.x;
    if (blockIdx.x >= M_) {          // ---- prepack branch ----
        int idx = (blockIdx.x - M_) * 128 + t;
        int m = idx >> 17, rem = idx & 0x1FFFF;
        int k = rem >> 8, nu = rem & 255;
        const float* ww = (m == 0) ? wq : (m == 1) ? wk : (m == 2) ? wv : wo;
        wpk[idx] = pkbf(ww[k * 512 + 2 * nu], ww[k * 512 + 2 * nu + 1]);
        return;
    }
    int row = blockIdx.x;
    float4 v = ((const float4*)(x + (size_t)row * D_))[t];
    float s  = v.x + v.y + v.z + v.w;
    float sq = v.x*v.x + v.y*v.y + v.z*v.z + v.w*v.w;
    #pragma unroll
    for (int off = 16; off; off >>= 1) {
        s  += __shfl_xor_sync(0xffffffffu, s,  off);
        sq += __shfl_xor_sync(0xffffffffu, sq, off);
    }
    __shared__ float ss[4], sq4[4];
    int wid = t >> 5, ln = t & 31;
    if (ln == 0) { ss[wid] = s; sq4[wid] = sq; }
    __syncthreads();
    s  = ss[0]  + ss[1]  + ss[2]  + ss[3];
    sq = sq4[0] + sq4[1] + sq4[2] + sq4[3];
    float mean = s * (1.0f / D_);
    float var  = sq * (1.0f / D_) - mean * mean;
    float rstd = rsqrtf(var + 1e-5f);
    int n = row & (N_ - 1);
    float4 pv = ((const float4*)(pe + (size_t)n * D_))[t];
    float4 wv4 = ((const float4*)w)[t];
    float4 bv4 = ((const float4*)bias)[t];
    float ox = (v.x - mean) * rstd * wv4.x + bv4.x + pv.x;
    float oy = (v.y - mean) * rstd * wv4.y + bv4.y + pv.y;
    float oz = (v.z - mean) * rstd * wv4.z + bv4.z + pv.z;
    float ow = (v.w - mean) * rstd * wv4.w + bv4.w + pv.w;
    ((uint2*)(h + (size_t)row * HP))[t] = make_uint2(pkbf(ox, oy), pkbf(oz, ow));
}

// ================= bf16 tensor-core GEMM, static 3-stage pipeline ==========
// MODE 0: fused QKV  — A=g_h, weight by blockIdx.x>>2; Q pre-scaled by SCQ7;
//                      bias=bv for wsel==2; out bf16 -> g_qkv
// MODE 1: out proj   — A=g_ao, weight wo, +bo +residual x, out fp32
template<int MODE>
__global__ __launch_bounds__(256, 2) void gemm_bf16(
    const unsigned* __restrict__ Apk, const unsigned* __restrict__ wpk,
    const float* __restrict__ bias, const float* __restrict__ res,
    float* __restrict__ Cf, unsigned* __restrict__ Cu)
{
    extern __shared__ unsigned dsm[];
    unsigned* As = dsm;           // 3 bufs x 128 x 36
    unsigned* Bs = dsm + 13824;   // 3 bufs x 64 x 68

    int tid  = threadIdx.x, lane = tid & 31, warp = tid >> 5;
    int li = lane >> 3, lr = lane & 7;
    int g = lane >> 2, t = lane & 3;
    int wm = (warp >> 2) * 64, wn = (warp & 3) * 32;
    int wn2 = (warp & 3) * 16;

    int cb    = blockIdx.x;
    int wsel  = (MODE == 0) ? (cb >> 2) : 3;
    int ncol0 = (MODE == 0) ? (cb & 3) * 128 : cb * 128;
    const unsigned* Bb = wpk + wsel * (512 * 256) + ncol0 / 2;
    const unsigned* Ab = Apk + (size_t)blockIdx.y * 128 * HP;

    int ar = tid >> 1, apc = (tid & 1) * 16;
    int br = tid >> 2, bcc = (tid & 3) * 16;
    unsigned sA = (unsigned)__cvta_generic_to_shared(As);
    unsigned sB = (unsigned)__cvta_generic_to_shared(Bs);

    int arow = 8 * (li & 1) + lr;
    int acol = (li >> 1) * 4;
    int bcol = (li >> 1) * 4;

    float acc[4][4][4];
    #pragma unroll
    for (int mi = 0; mi < 4; mi++)
        #pragma unroll
        for (int ni = 0; ni < 4; ni++)
            #pragma unroll
            for (int r = 0; r < 4; r++) acc[mi][ni][r] = 0.0f;

    auto stage = [&](int s, int buf) {
        unsigned da = sA + (buf * 4608 + ar * 36 + apc) * 4;
        const unsigned* ga = Ab + (size_t)ar * HP + s * 32 + apc;
        #pragma unroll
        for (int i = 0; i < 4; i++) cp16(da + i * 16, ga + i * 4);
        unsigned db = sB + (buf * 4352 + br * 68 + bcc) * 4;
        const unsigned* gb = Bb + (size_t)(s * 64 + br) * 256 + bcc;
        #pragma unroll
        for (int i = 0; i < 4; i++) cp16(db + i * 16, gb + i * 4);
        CPCOMMIT();
    };

    stage(0, 0);
    stage(1, 1);
    CPWAIT(1);
    __syncthreads();

#define GBODY(s, BUF, PBUF)                                                  \
    do {                                                                     \
        if ((s) + 2 < 8) stage((s) + 2, (PBUF));                             \
        unsigned baseA = sA + (BUF) * 18432;                                 \
        unsigned baseB = sB + (BUF) * 17408;                                 \
        _Pragma("unroll")                                                    \
        for (int kk = 0; kk < 4; kk++) {                                     \
            unsigned af[4][4];                                               \
            _Pragma("unroll")                                                \
            for (int mi = 0; mi < 4; mi++)                                   \
                ldsm4(af[mi], baseA +                                        \
                      ((wm + mi * 16 + arow) * 36 + kk * 8 + acol) * 4);     \
            unsigned bb[8];                                                  \
            _Pragma("unroll")                                                \
            for (int j = 0; j < 2; j++)                                      \
                ldsm4t(bb + 4 * j, baseB +                                   \
                       ((kk * 16 + arow) * 68 + wn2 + j * 8 + bcol) * 4);    \
            _Pragma("unroll")                                                \
            for (int mi = 0; mi < 4; mi++)                                   \
                _Pragma("unroll")                                            \
                for (int ni = 0; ni < 4; ni++)                               \
                    mma_bf16(acc[mi][ni], af[mi][0], af[mi][1], af[mi][2],   \
                             af[mi][3],                                      \
                             bb[4 * (ni >> 1) + 2 * (ni & 1)],               \
                             bb[4 * (ni >> 1) + 2 * (ni & 1) + 1]);          \
        }                                                                    \
        if ((s) < 6) { CPWAIT(1); __syncthreads(); }                         \
        else if ((s) == 6) { CPWAIT(0); __syncthreads(); }                   \
    } while (0)

    GBODY(0, 0, 2); GBODY(1, 1, 0); GBODY(2, 2, 1); GBODY(3, 0, 2);
    GBODY(4, 1, 0); GBODY(5, 2, 1); GBODY(6, 0, 2); GBODY(7, 1, 0);
#undef GBODY

    #pragma unroll
    for (int mi = 0; mi < 4; mi++) {
        int r0 = blockIdx.y * 128 + wm + mi * 16 + g;
        #pragma unroll
        for (int ni = 0; ni < 4; ni++) {
            int ec = ncol0 + wn + ni * 8 + 2 * t;
            float v0 = acc[mi][ni][0], v1 = acc[mi][ni][1];
            float v2 = acc[mi][ni][2], v3 = acc[mi][ni][3];
            if (MODE == 0) {
                if (wsel == 0) {
                    v0 *= SCQ7; v1 *= SCQ7; v2 *= SCQ7; v3 *= SCQ7;
                }
                if (wsel == 2) {
                    float2 bb2 = *(const float2*)(bias + ec);
                    v0 += bb2.x; v1 += bb2.y; v2 += bb2.x; v3 += bb2.y;
                }
                unsigned ucol = wsel * 256 + (ec >> 1);
                Cu[(size_t)r0 * QKVP + ucol]       = pkbf(v0, v1);
                Cu[(size_t)(r0 + 8) * QKVP + ucol] = pkbf(v2, v3);
            } else {
                float2 bb2 = *(const float2*)(bias + ec);
                size_t o0 = (size_t)r0 * 512 + ec;
                size_t o1 = (size_t)(r0 + 8) * 512 + ec;
                float2 ra = *(const float2*)(res + o0);
                float2 rb = *(const float2*)(res + o1);
                *(float2*)(Cf + o0) = make_float2(v0 + bb2.x + ra.x, v1 + bb2.y + ra.y);
                *(float2*)(Cf + o1) = make_float2(v2 + bb2.x + rb.x, v3 + bb2.y + rb.y);
            }
        }
    }
}

// ================= flash attention: intra-warp S/PV pingpong (R14) =========
// 256 thr / 8 warps, q-tile 128, key chunk 64, 2 CTAs/SM, 4 static buffers,
// prefetch distance 3. Body(c): softmax(c) from loop-carried s -> pa;
// zero s; issue S(c+1) MMAs; PV(c)+L(c) MMAs from pa (row-sum on tensor pipe,
// where it overlaps — measured faster than ALU accumulation in the serial
// softmax section).
__global__ __launch_bounds__(256, 2) void attn_kernel(
    const unsigned* __restrict__ qkv, unsigned* __restrict__ ao)
{
    extern __shared__ unsigned asm_[];
    unsigned* Ks = asm_;              // 4 bufs x 64 x 36
    unsigned* Vs = asm_ + 4 * 2304;   // 4 bufs x 64 x 36

    int tid = threadIdx.x, lane = tid & 31, warp = tid >> 5;
    int g = lane >> 2, t = lane & 3;
    int li = lane >> 3, lr = lane & 7;
    int bh = blockIdx.y, bb = bh >> 3, hh = bh & 7;
    int q0 = blockIdx.x * 128;
    const unsigned* base = qkv + (size_t)bb * N_ * QKVP + hh * 32;

    int kcr = tid >> 2, kcp = (tid & 3) * 8;   // copy: row, uint col
    unsigned sK = (unsigned)__cvta_generic_to_shared(Ks);
    unsigned sV = (unsigned)__cvta_generic_to_shared(Vs);

    // ldmatrix lane constants
    int krow = (li >> 1) * 8 + lr;
    int kcol = (li & 1) * 4;
    int vrow = (li & 1) * 8 + lr;
    int vcol = (li >> 1) * 4;

    auto cpKV = [&](int c0, int buf) {
        const unsigned* src = base + (size_t)(c0 + kcr) * QKVP + 256 + kcp;
        unsigned dK = sK + (buf * 2304 + kcr * 36 + kcp) * 4;
        cp16(dK, src); cp16(dK + 16, src + 4);
        unsigned dV = sV + (buf * 2304 + kcr * 36 + kcp) * 4;
        cp16(dV, src + 256); cp16(dV + 16, src + 260);
        CPCOMMIT();
    };

    // prologue: chunks 0,1,2 in flight + Q fragments
    cpKV(0, 0);
    cpKV(64, 1);
    cpKV(128, 2);
    unsigned qf[4][4];
    {
        const unsigned* q0p = base + (size_t)(q0 + warp * 16 + g) * QKVP;
        const unsigned* q1p = q0p + 8 * QKVP;
        #pragma unroll
        for (int kk = 0; kk < 4; kk++) {
            qf[kk][0] = q0p[kk * 8 + t];
            qf[kk][1] = q1p[kk * 8 + t];
            qf[kk][2] = q0p[kk * 8 + t + 4];
            qf[kk][3] = q1p[kk * 8 + t + 4];
        }
    }
    CPWAIT(1);          // chunks 0,1 resident (chunk 2 may still fly)
    __syncthreads();

    float o[8][4], s[8][4];
    #pragma unroll
    for (int ni = 0; ni < 8; ni++)
        #pragma unroll
        for (int r = 0; r < 4; r++) { o[ni][r] = 0.0f; s[ni][r] = 0.0f; }
    float l9[4] = {0.0f, 0.0f, 0.0f, 0.0f};   // P @ ones -> row sums

// S += Q @ K(buffer NB)^T
#define SMMA(NB)                                                             \
    do {                                                                     \
        unsigned baseK = sK + (NB) * 9216;                                   \
        _Pragma("unroll")                                                    \
        for (int kk = 0; kk < 4; kk++) {                                     \
            unsigned kb[16];                                                 \
            _Pragma("unroll")                                                \
            for (int j = 0; j < 4; j++)                                      \
                ldsm4(kb + 4 * j, baseK +                                    \
                      ((j * 16 + krow) * 36 + kk * 8 + kcol) * 4);           \
            _Pragma("unroll")                                                \
            for (int ni = 0; ni < 8; ni++)                                   \
                mma_bf16(s[ni], qf[kk][0], qf[kk][1], qf[kk][2], qf[kk][3],  \
                         kb[4 * (ni >> 1) + 2 * (ni & 1)],                   \
                         kb[4 * (ni >> 1) + 2 * (ni & 1) + 1]);              \
        }                                                                    \
    } while (0)

    SMMA(0);

// Body(c). BUF=c&3 (V read), NBUF=(c+1)&3 (K read), CPBUF=(c+3)&3 (cp tgt).
#define CHUNK(c, BUF, NBUF, CPBUF, WMODE, LAST)                              \
    do {                                                                     \
        if ((c) + 3 < 32) cpKV(((c) + 3) * 64, (CPBUF));                     \
        unsigned pa[4][4];                                                   \
        _Pragma("unroll")                                                    \
        for (int ni = 0; ni < 8; ni++) {                                     \
            int v0 = __float2int_rn(s[ni][0] + MAGICF);                      \
            int v1 = __float2int_rn(s[ni][1] + MAGICF);                      \
            int v2 = __float2int_rn(s[ni][2] + MAGICF);                      \
            int v3 = __float2int_rn(s[ni][3] + MAGICF);                      \
            int kk = ni >> 1, hf = ni & 1;                                   \
            pa[kk][2 * hf]     = __byte_perm(v0, v1, 0x5410);                \
            pa[kk][2 * hf + 1] = __byte_perm(v2, v3, 0x5410);                \
        }                                                                    \
        if (!(LAST)) {                                                       \
            _Pragma("unroll")                                                \
            for (int ni = 0; ni < 8; ni++) {                                 \
                s[ni][0] = 0.0f; s[ni][1] = 0.0f;                            \
                s[ni][2] = 0.0f; s[ni][3] = 0.0f;                            \
            }                                                                \
            SMMA(NBUF);                                                      \
        }                                                                    \
        unsigned baseV = sV + (BUF) * 9216;                                  \
        _Pragma("unroll")                                                    \
        for (int kk = 0; kk < 4; kk++) {                                     \
            unsigned vb[16];                                                 \
            _Pragma("unroll")                                                \
            for (int j = 0; j < 4; j++)                                      \
                ldsm4t(vb + 4 * j, baseV +                                   \
                       ((kk * 16 + vrow) * 36 + j * 8 + vcol) * 4);          \
            _Pragma("unroll")                                                \
            for (int ni = 0; ni < 8; ni++)                                   \
                mma_bf16(o[ni], pa[kk][0], pa[kk][1], pa[kk][2], pa[kk][3],  \
                         vb[4 * (ni >> 1) + 2 * (ni & 1)],                   \
                         vb[4 * (ni >> 1) + 2 * (ni & 1) + 1]);              \
            mma_bf16(l9, pa[kk][0], pa[kk][1], pa[kk][2], pa[kk][3],         \
                     ONESBF, ONESBF);                                        \
        }                                                                    \
        if ((WMODE) == 0) { CPWAIT(1); __syncthreads(); }                    \
        else if ((WMODE) == 1) { CPWAIT(0); __syncthreads(); }               \
    } while (0)

    for (int c0 = 0; c0 < 28; c0 += 4) {
        CHUNK(c0,     0, 1, 3, 0, 0);
        CHUNK(c0 + 1, 1, 2, 0, 0, 0);
        CHUNK(c0 + 2, 2, 3, 1, 0, 0);
        CHUNK(c0 + 3, 3, 0, 2, 0, 0);
    }
    CHUNK(28, 0, 1, 3, 0, 0);
    CHUNK(29, 1, 2, 0, 1, 0);
    CHUNK(30, 2, 3, 1, 2, 0);
    CHUNK(31, 3, 0, 2, 2, 1);
#undef CHUNK
#undef SMMA

    // epilogue -> g_ao (bf16 packed); l9[0]/l9[2] hold the row sums
    float i0 = 1.0f / l9[0], i1 = 1.0f / l9[2];
    int r0 = bb * N_ + q0 + warp * 16 + g;
    unsigned* a0p = ao + (size_t)r0 * AOP + hh * 32;
    unsigned* a1p = a0p + 8 * AOP;
    #pragma unroll
    for (int ni = 0; ni < 8; ni++) {
        a0p[ni * 4 + t] = pkbf(o[ni][0] * i0, o[ni][1] * i0);
        a1p[ni * 4 + t] = pkbf(o[ni][2] * i1, o[ni][3] * i1);
    }
}

// ================= launch ==========================
extern "C" void kernel_launch(void* const* d_in, const int* in_sizes, int n_in,
                              void* d_out, int out_size)
{
    const float* x    = (const float*)d_in[0];
    const float* ln_w = (const float*)d_in[1];
    const float* ln_b = (const float*)d_in[2];
    const float* wq   = (const float*)d_in[3];
    const float* wk   = (const float*)d_in[4];
    const float* wv   = (const float*)d_in[5];
    const float* bv   = (const float*)d_in[6];
    const float* wo   = (const float*)d_in[7];
    const float* bo   = (const float*)d_in[8];
    const float* pe   = (const float*)d_in[9];
    float* out = (float*)d_out;

    unsigned *hp, *qkvp, *aop, *wpk;
    cudaGetSymbolAddress((void**)&hp,   g_h);
    cudaGetSymbolAddress((void**)&qkvp, g_qkv);
    cudaGetSymbolAddress((void**)&aop,  g_ao);
    cudaGetSymbolAddress((void**)&wpk,  g_wpk);

    const int GSM  = 3 * (4608 + 4352) * 4;   // 107520 B
    const int ASMB = 4 * 2304 * 2 * 4;        // 73728 B
    cudaFuncSetAttribute(gemm_bf16<0>,
                         cudaFuncAttributeMaxDynamicSharedMemorySize, GSM);
    cudaFuncSetAttribute(gemm_bf16<1>,
                         cudaFuncAttributeMaxDynamicSharedMemorySize, GSM);
    cudaFuncSetAttribute(attn_kernel,
                         cudaFuncAttributeMaxDynamicSharedMemorySize, ASMB);

    // 1) LayerNorm + pe + weight prepack (one fused launch)
    ln_prepack_kernel<<<M_ + 4096, 128>>>(x, ln_w, ln_b, pe, hp,
                                          wq, wk, wv, wo, wpk);

    // 2) fused QKV projection (Q pre-scaled by SCQ7)
    gemm_bf16<0><<<dim3(12, M_ / 128), 256, GSM>>>(hp, wpk, bv, nullptr,
                                                   nullptr, qkvp);

    // 3) flash attention: pingpong S/PV, L via MMA
    attn_kernel<<<dim3(N_ / 128, B_ * H_), 256, ASMB>>>(qkvp, aop);

    // 4) output projection + bias + residual
    gemm_bf16<1><<<dim3(4, M_ / 128), 256, GSM>>>(aop, wpk, bo, x, out, nullptr);
}